// round 16
// baseline (speedup 1.0000x reference)
#include <cuda_runtime.h>
#include <cuda_bf16.h>
#include <cstdint>

#define HW   16384
#define Wdim 128

// ---------------- scratch (bf16 intermediates) ----------------
__device__ __nv_bfloat16 g_h [16ULL*256*16384];  // pf out: a(0..127) | xh(128..255)
__device__ __nv_bfloat16 g_t1[16ULL*128*16384];  // l3pre(0..63) | l5pre(64..127)
__device__ __nv_bfloat16 g_x3[16ULL*128*16384];  // gate*xh (0..127)

// ---------------- helpers ----------------
__device__ __forceinline__ uint32_t smem_u32(const void* p){
  uint32_t a;
  asm("{ .reg .u64 t; cvta.to.shared.u64 t, %1; cvt.u32.u64 %0, t; }" : "=r"(a) : "l"(p));
  return a;
}
__device__ __forceinline__ void cp16(uint32_t s, const void* g){
  asm volatile("cp.async.cg.shared.global [%0], [%1], 16;" :: "r"(s), "l"(g) : "memory");
}
__device__ __forceinline__ void cp_commit(){ asm volatile("cp.async.commit_group;" ::: "memory"); }
__device__ __forceinline__ void cp_wait0(){ asm volatile("cp.async.wait_group 0;" ::: "memory"); }
__device__ __forceinline__ void cp_wait1(){ asm volatile("cp.async.wait_group 1;" ::: "memory"); }
__device__ __forceinline__ void mma_bf16(float* d, const uint32_t* a, const uint32_t* b){
  asm volatile(
    "mma.sync.aligned.m16n8k16.row.col.f32.bf16.bf16.f32 "
    "{%0,%1,%2,%3}, {%4,%5,%6,%7}, {%8,%9}, {%0,%1,%2,%3};"
    : "+f"(d[0]), "+f"(d[1]), "+f"(d[2]), "+f"(d[3])
    : "r"(a[0]), "r"(a[1]), "r"(a[2]), "r"(a[3]), "r"(b[0]), "r"(b[1]));
}
__device__ __forceinline__ void ldsm4(uint32_t* r, uint32_t a){
  asm volatile("ldmatrix.sync.aligned.m8n8.x4.shared.b16 {%0,%1,%2,%3}, [%4];"
    : "=r"(r[0]), "=r"(r[1]), "=r"(r[2]), "=r"(r[3]) : "r"(a));
}
__device__ __forceinline__ void ldsm4t(uint32_t* r, uint32_t a){
  asm volatile("ldmatrix.sync.aligned.m8n8.x4.trans.shared.b16 {%0,%1,%2,%3}, [%4];"
    : "=r"(r[0]), "=r"(r[1]), "=r"(r[2]), "=r"(r[3]) : "r"(a));
}
__device__ __forceinline__ uint32_t pkbf(float a, float b){
  __nv_bfloat162 t = __floats2bfloat162_rn(a, b);
  return *reinterpret_cast<uint32_t*>(&t);
}
__device__ __forceinline__ float2 ldbf2(const __nv_bfloat16* p){
  return __bfloat1622float2(*(const __nv_bfloat162*)p);
}

// ---------------------------------------------------------------------------
// pf: LN folded into weights.  h = rs*(W'@x) - mu*rs*c1 + (c2 + bias),
// W' = W*lnw (bf16), c1 = sum W', c2 = sum W*lnb.  GEMM on raw bf16 x.
// 64-px tiles, 1024 threads, output staged through dead fp32 X buffer.
// ---------------------------------------------------------------------------
#define PF_WS   0        // 256 x 136 bf16 = 69632 (W')
#define PF_X0   69632    // 128 x 68 f32 = 34816
#define PF_X1   104448
#define PF_XN   139264   // 128 x 72 bf16 = 18432
#define PF_C1   157696   // 256 f32
#define PF_C2   158720   // 256 f32
#define PF_MU   159744   // 64 f32
#define PF_RS   160000
#define PF_MR   160256
#define PF_PART 160512   // 2048 f32 = 8192
#define PF_TOT  168704

__global__ __launch_bounds__(1024, 1)
void pf_kernel(const float* __restrict__ in,
               const float* __restrict__ lnw, const float* __restrict__ lnb,
               const float* __restrict__ w, const float* __restrict__ bias,
               __nv_bfloat16* __restrict__ out, int ntiles)
{
  extern __shared__ char smc[];
  __nv_bfloat16* Ws = (__nv_bfloat16*)(smc + PF_WS);
  float* Xb0 = (float*)(smc + PF_X0);
  float* Xb1 = (float*)(smc + PF_X1);
  __nv_bfloat16* Xn = (__nv_bfloat16*)(smc + PF_XN);
  float* sC1 = (float*)(smc + PF_C1);
  float* sC2 = (float*)(smc + PF_C2);
  float* sMu = (float*)(smc + PF_MU);
  float* sRs = (float*)(smc + PF_RS);
  float* sMR = (float*)(smc + PF_MR);
  float* sPart = (float*)(smc + PF_PART);
  const uint32_t sbase = smem_u32(smc);
  const uint32_t xu0 = sbase + PF_X0, xu1 = sbase + PF_X1;

  const int tid = threadIdx.x;
  const int wid = tid >> 5, lid = tid & 31;
  const int b   = blockIdx.y;

  if (tid < 256){ sC1[tid] = 0.f; sC2[tid] = 0.f; }
  __syncthreads();

  // stage W' = W*lnw (bf16), accumulate c1 (sum of rounded W') and c2 (W·lnb)
  for (int i = tid; i < 256*32; i += 1024){
    int oc = i >> 5, c4 = (i & 31) << 2;
    float4 wv = *(const float4*)(w + oc*128 + c4);
    float4 lw = *(const float4*)(lnw + c4);
    float4 lb = *(const float4*)(lnb + c4);
    uint32_t p0 = pkbf(wv.x*lw.x, wv.y*lw.y);
    uint32_t p1 = pkbf(wv.z*lw.z, wv.w*lw.w);
    uint32_t* d = (uint32_t*)(Ws + oc*136 + c4);
    d[0] = p0; d[1] = p1;
    float2 f0 = __bfloat1622float2(*(__nv_bfloat162*)&p0);
    float2 f1 = __bfloat1622float2(*(__nv_bfloat162*)&p1);
    atomicAdd(&sC1[oc], f0.x + f0.y + f1.x + f1.y);
    atomicAdd(&sC2[oc], wv.x*lb.x + wv.y*lb.y + wv.z*lb.z + wv.w*lb.w);
  }
  __syncthreads();

  const int wm = wid & 15, wn = wid >> 4;     // 16 oc groups x 2 px groups
  const int oc0 = wm*16, pxw = wn*32;
  const int r = lid >> 2, cq = lid & 3;
  const int mh = lid >> 3, rr = lid & 7;
  const int oA = oc0 + r, oB = oc0 + r + 8;
  const float c1A = sC1[oA], cc2A = sC2[oA] + bias[oA];
  const float c1B = sC1[oB], cc2B = sC2[oB] + bias[oB];

  const uint32_t aBase  = sbase + PF_WS
      + (uint32_t)(((oc0 + rr + (mh&1)*8)*136 + (mh>>1)*8) * 2);
  const uint32_t bBase0 = sbase + PF_XN
      + (uint32_t)(((rr + (mh&1)*8)*72 + pxw + (mh>>1)*8) * 2);
  const uint32_t bBase1 = bBase0 + 32;        // +16 px

  auto stage = [&](int t){
    const int px0 = (blockIdx.x * ntiles + t) * 64;
    const uint32_t xb = (t & 1) ? xu1 : xu0;
    const float* ipx = in + (size_t)b*(128LL*HW) + px0;
    #pragma unroll 2
    for (int i = tid; i < 128*16; i += 1024){
      int ic = i >> 4, pc = (i & 15) << 2;
      cp16(xb + (uint32_t)(ic*68 + pc)*4u, ipx + (size_t)ic*HW + pc);
    }
    cp_commit();
  };
  stage(0);

  for (int t = 0; t < ntiles; t++){
    if (t+1 < ntiles){ stage(t+1); cp_wait1(); }
    else             { cp_wait0(); }
    __syncthreads();                        // sync1: data ready
    float* Xs = (t & 1) ? Xb1 : Xb0;
    uint32_t* XsW = (uint32_t*)Xs;
    const int px0 = (blockIdx.x * ntiles + t) * 64;

    // stats partials + bf16 convert (both read Xs, independent)
    {
      const int px = tid & 63, q = tid >> 6;
      float s = 0.f, s2 = 0.f;
      #pragma unroll
      for (int ic = 0; ic < 8; ic++){
        float v = Xs[(q*8 + ic)*68 + px]; s += v; s2 += v*v;
      }
      sPart[tid] = s; sPart[1024 + tid] = s2;
    }
    #pragma unroll 4
    for (int i = tid; i < 128*32; i += 1024){
      int ch = i >> 5, pxp = (i & 31) << 1;
      float2 v = *(const float2*)(Xs + ch*68 + pxp);
      *(uint32_t*)(Xn + ch*72 + pxp) = pkbf(v.x, v.y);
    }
    __syncthreads();                        // sync2: Xn + partials ready

    if (tid < 64){
      float ss = 0.f, qq = 0.f;
      #pragma unroll
      for (int j = 0; j < 16; j++){
        ss += sPart[tid + 64*j];
        qq += sPart[1024 + tid + 64*j];
      }
      float mu = ss * (1.f/128.f);
      float rs = rsqrtf(qq*(1.f/128.f) - mu*mu + 1e-6f);
      sMu[tid] = mu; sRs[tid] = rs; sMR[tid] = mu*rs;
    }

    float acc[4][4];
    #pragma unroll
    for (int ni = 0; ni < 4; ni++)
      #pragma unroll
      for (int j = 0; j < 4; j++) acc[ni][j] = 0.f;

    #pragma unroll
    for (int ks = 0; ks < 8; ks++){
      uint32_t af[4], b0[4], b1[4];
      ldsm4 (af, aBase  + (uint32_t)ks*32);
      ldsm4t(b0, bBase0 + (uint32_t)ks*2304);
      ldsm4t(b1, bBase1 + (uint32_t)ks*2304);
      mma_bf16(acc[0], af, b0);
      mma_bf16(acc[1], af, b0 + 2);
      mma_bf16(acc[2], af, b1);
      mma_bf16(acc[3], af, b1 + 2);
    }
    __syncthreads();                        // sync3: mu/rs ready; Xs dead

    // affine epilogue -> stage into XsW (pitch 34 words)
    {
      const int pw0 = (pxw >> 1) + cq;
      #pragma unroll
      for (int ni = 0; ni < 4; ni++){
        const int pxl = pxw + ni*8 + cq*2;
        float2 rsv = *(const float2*)(sRs + pxl);
        float2 mrv = *(const float2*)(sMR + pxl);
        float h0 = rsv.x*acc[ni][0] - mrv.x*c1A + cc2A;
        float h1 = rsv.y*acc[ni][1] - mrv.y*c1A + cc2A;
        float h2 = rsv.x*acc[ni][2] - mrv.x*c1B + cc2B;
        float h3 = rsv.y*acc[ni][3] - mrv.y*c1B + cc2B;
        XsW[oA*34 + pw0 + ni*4] = pkbf(h0, h1);
        XsW[oB*34 + pw0 + ni*4] = pkbf(h2, h3);
      }
    }
    __syncthreads();                        // sync4

    __nv_bfloat16* ob = out + (size_t)b*256*HW + px0;
    for (int i = tid; i < 256*16; i += 1024){
      int oc = i >> 4, seg = i & 15;
      uint2 v = *(const uint2*)(XsW + oc*34 + seg*2);
      *(uint2*)(ob + (size_t)oc*HW + seg*4) = v;
    }
    __syncthreads();                        // sync5: guard XsW reuse
  }
}

// ---------------------------------------------------------------------------
// fuse2: attn + pl, 128-px tiles (A-fragment reuse x2, fewer syncs/px).
// gate already contains gate*xh. Single Ts buffer (top sync orders reuse).
// ---------------------------------------------------------------------------
#define F2_W1   0        // 128 x 72 bf16 = 18432
#define F2_W2   18432    // 128 x 136 bf16 = 34816
#define F2_PRE  53248    // 2 x 34816
#define F2_GATE 122880   // 2 x 34816
#define F2_T    192512   // 34816
#define F2_TOT  227328
#define TBUF2   34816

__global__ __launch_bounds__(1024, 1)
void fuse2_kernel(const __nv_bfloat16* __restrict__ pre,
                  const __nv_bfloat16* __restrict__ gate,
                  const float* __restrict__ w1A, const float* __restrict__ w1B,
                  const float* __restrict__ b1A, const float* __restrict__ b1B,
                  const float* __restrict__ plw, const float* __restrict__ plb,
                  const float* __restrict__ scal, const float* __restrict__ xres,
                  float* __restrict__ out, int ntiles)
{
  extern __shared__ char smc[];
  __nv_bfloat16* W1s = (__nv_bfloat16*)(smc + F2_W1);
  __nv_bfloat16* W2s = (__nv_bfloat16*)(smc + F2_W2);
  __nv_bfloat16* Ts  = (__nv_bfloat16*)(smc + F2_T);
  const uint32_t sbase = smem_u32(smc);

  const int tid = threadIdx.x;
  const int wid = tid >> 5, lid = tid & 31;
  const int b   = blockIdx.y;

  for (int i = tid; i < 128*16; i += 1024){
    int oc = i >> 4, k4 = (i & 15) << 2;
    float4 v = (oc < 64) ? *(const float4*)(w1A + oc*64 + k4)
                         : *(const float4*)(w1B + (oc-64)*64 + k4);
    uint32_t* d = (uint32_t*)(W1s + oc*72 + k4);
    d[0] = pkbf(v.x, v.y); d[1] = pkbf(v.z, v.w);
  }
  for (int i = tid; i < 128*32; i += 1024){
    int oc = i >> 5, c4 = (i & 31) << 2;
    float4 v = *(const float4*)(plw + oc*128 + c4);
    uint32_t* d = (uint32_t*)(W2s + oc*136 + c4);
    d[0] = pkbf(v.x, v.y); d[1] = pkbf(v.z, v.w);
  }

  const int wm = wid & 7, wn = wid >> 3;   // 8 oc groups x 4 px groups (32px)
  const int oc0 = wm*16, pxw = wn*32;
  const int r = lid >> 2, cq = lid & 3;
  const int mh = lid >> 3, rr = lid & 7;
  const int oA = oc0 + r, oB = oc0 + r + 8;
  const int koff = (oc0 >= 64) ? 64 : 0;

  const float bz1A = (oA < 64) ? b1A[oA] : b1B[oA-64];
  const float bz1B = (oB < 64) ? b1A[oB] : b1B[oB-64];
  const float bz2A = plb[oA], bz2B = plb[oB];
  const float scA  = scal[oA], scB = scal[oB];

  const uint32_t a1Base = sbase + F2_W1
      + (uint32_t)(((oc0 + rr + (mh&1)*8)*72 + (mh>>1)*8) * 2);
  const uint32_t a2Base = sbase + F2_W2
      + (uint32_t)(((oc0 + rr + (mh&1)*8)*136 + (mh>>1)*8) * 2);
  const uint32_t b1Off  =
      (uint32_t)(((koff + rr + (mh&1)*8)*136 + pxw + (mh>>1)*8) * 2);
  const uint32_t b2Base = sbase + F2_T
      + (uint32_t)(((rr + (mh&1)*8)*136 + pxw + (mh>>1)*8) * 2);

  auto stage = [&](int t){
    const int px0 = (blockIdx.x * ntiles + t) * 128;
    const uint32_t buf = (uint32_t)(t & 1) * TBUF2;
    const __nv_bfloat16* p1 = pre  + (size_t)b*(128LL*HW) + px0;
    const __nv_bfloat16* p2 = gate + (size_t)b*(128LL*HW) + px0;
    #pragma unroll 2
    for (int i = tid; i < 128*16; i += 1024){
      int ic = i >> 4, pc = (i & 15) << 3;
      uint32_t off = (uint32_t)(ic*136 + pc)*2u;
      cp16(sbase + F2_PRE  + buf + off, p1 + (size_t)ic*HW + pc);
      cp16(sbase + F2_GATE + buf + off, p2 + (size_t)ic*HW + pc);
    }
    cp_commit();
  };
  stage(0);

  for (int t = 0; t < ntiles; t++){
    if (t+1 < ntiles){ stage(t+1); cp_wait1(); }
    else             { cp_wait0(); }
    __syncthreads();
    const int buf = (t & 1);
    const __nv_bfloat16* Gs = (const __nv_bfloat16*)(smc + F2_GATE + buf*TBUF2);
    const uint32_t b1Base = sbase + F2_PRE + (uint32_t)buf*TBUF2 + b1Off;
    const int px0 = (blockIdx.x * ntiles + t) * 128;

    // ---- GEMM1: K=64 ----
    float a1[4][4];
    #pragma unroll
    for (int ni = 0; ni < 4; ni++)
      #pragma unroll
      for (int j = 0; j < 4; j++) a1[ni][j] = 0.f;

    #pragma unroll
    for (int ks = 0; ks < 4; ks++){
      uint32_t af[4], b0[4], b1v[4];
      ldsm4 (af, a1Base + (uint32_t)ks*32);
      ldsm4t(b0,  b1Base + (uint32_t)ks*4352);
      ldsm4t(b1v, b1Base + (uint32_t)ks*4352 + 32);
      mma_bf16(a1[0], af, b0);
      mma_bf16(a1[1], af, b0 + 2);
      mma_bf16(a1[2], af, b1v);
      mma_bf16(a1[3], af, b1v + 2);
    }

    // epilogue1: t = (acc + b1) * (gate*xh) -> Ts
    #pragma unroll
    for (int ni = 0; ni < 4; ni++){
      const int pxl = pxw + ni*8 + cq*2;
      float2 gA = ldbf2(Gs + oA*136 + pxl);
      *(uint32_t*)(Ts + oA*136 + pxl) =
        pkbf((a1[ni][0] + bz1A)*gA.x, (a1[ni][1] + bz1A)*gA.y);
      float2 gB = ldbf2(Gs + oB*136 + pxl);
      *(uint32_t*)(Ts + oB*136 + pxl) =
        pkbf((a1[ni][2] + bz1B)*gB.x, (a1[ni][3] + bz1B)*gB.y);
    }
    __syncthreads();

    // ---- GEMM2: K=128 ----
    float a2[4][4];
    #pragma unroll
    for (int ni = 0; ni < 4; ni++)
      #pragma unroll
      for (int j = 0; j < 4; j++) a2[ni][j] = 0.f;

    #pragma unroll
    for (int ks = 0; ks < 8; ks++){
      uint32_t af[4], b0[4], b1v[4];
      ldsm4 (af, a2Base + (uint32_t)ks*32);
      ldsm4t(b0,  b2Base + (uint32_t)ks*4352);
      ldsm4t(b1v, b2Base + (uint32_t)ks*4352 + 32);
      mma_bf16(a2[0], af, b0);
      mma_bf16(a2[1], af, b0 + 2);
      mma_bf16(a2[2], af, b1v);
      mma_bf16(a2[3], af, b1v + 2);
    }

    // epilogue2: (acc + plb)*scale + xres -> fp32 out
    {
      const int pc = px0 + pxw + cq*2;
      float* opA = out + ((size_t)b*128 + oA)*HW + pc;
      float* opB = out + ((size_t)b*128 + oB)*HW + pc;
      const float* shA = xres + ((size_t)b*128 + oA)*HW + pc;
      const float* shB = xres + ((size_t)b*128 + oB)*HW + pc;
      #pragma unroll
      for (int ni = 0; ni < 4; ni++){
        float2 sA = *(const float2*)(shA + ni*8);
        float2 sB = *(const float2*)(shB + ni*8);
        *(float2*)(opA + ni*8) = make_float2((a2[ni][0] + bz2A)*scA + sA.x,
                                             (a2[ni][1] + bz2A)*scA + sA.y);
        *(float2*)(opB + ni*8) = make_float2((a2[ni][2] + bz2B)*scB + sB.x,
                                             (a2[ni][3] + bz2B)*scB + sB.y);
      }
    }
    // no trailing sync: next tile's top sync orders Ts/PRE/GATE reuse
  }
}

// ---------------------------------------------------------------------------
// branch-1: 32x64 tile; gate output pre-multiplied by xh. (r15, unchanged)
// ---------------------------------------------------------------------------
__global__ __launch_bounds__(256)
void branch1_kernel(const __nv_bfloat16* __restrict__ in, long long in_bs,
    const __nv_bfloat16* __restrict__ xh,
    const float* __restrict__ l3w1, const float* __restrict__ l3b1,
    const float* __restrict__ l3w2, const float* __restrict__ l3b2,
    const float* __restrict__ l3w3, const float* __restrict__ l3b3,
    const float* __restrict__ x3aw, const float* __restrict__ x3ab,
    const float* __restrict__ x3bw, const float* __restrict__ x3bb,
    __nv_bfloat16* __restrict__ l3pre, __nv_bfloat16* __restrict__ x3out,
    long long out_bs)
{
  __shared__ float sIN[42*75];
  __shared__ float sT1[42*73];
  __shared__ __nv_bfloat16 sU1[34*66];
  __shared__ __nv_bfloat16 sT2[40*74];
  __shared__ float wsh[42];

  const int c = blockIdx.z & 63, b = blockIdx.z >> 6;
  const int ty0 = blockIdx.y * 32, tx0 = blockIdx.x * 64;
  const int tid = threadIdx.x;

  if (tid < 42){
    float v;
    if      (tid < 3)  v = l3w1[c*3 + tid];
    else if (tid < 6)  v = l3w2[c*3 + tid-3];
    else if (tid < 31) v = l3w3[c*25 + tid-6];
    else if (tid < 34) v = x3aw[c*3 + tid-31];
    else if (tid < 37) v = x3bw[c*3 + tid-34];
    else if (tid == 37) v = l3b1[c];
    else if (tid == 38) v = l3b2[c];
    else if (tid == 39) v = l3b3[c];
    else if (tid == 40) v = x3ab[c];
    else                v = x3bb[c];
    wsh[tid] = v;
  }

  const __nv_bfloat16* ip = in + (long long)b*in_bs + (long long)c*HW;
  for (int i = tid; i < 42*74; i += 256){
    int sy = i / 74, sx = i - sy*74;
    int gy = ty0 + sy - 5, gx = tx0 + sx - 5;
    float v = 0.f;
    if ((unsigned)gy < 128u && (unsigned)gx < 128u) v = __bfloat162float(ip[gy*Wdim + gx]);
    sIN[sy*75 + sx] = v;
  }
  __syncthreads();

  {
    const float w0 = wsh[0], w1 = wsh[1], w2 = wsh[2], bz = wsh[37];
    for (int i = tid; i < 42*72; i += 256){
      int r = i / 72, x = i - r*72;
      const float* s = sIN + r*75 + x;
      sT1[r*73 + x] = w0*s[0] + w1*s[1] + w2*s[2] + bz;
    }
    const float a0 = wsh[31], a1 = wsh[32], a2 = wsh[33], ab = wsh[40];
    for (int i = tid; i < 34*64; i += 256){
      int r = i >> 6, x = i & 63;
      const float* s = sIN + (r+4)*75 + x + 4;
      sU1[r*66 + x] = __float2bfloat16(a0*s[0] + a1*s[1] + a2*s[2] + ab);
    }
  }
  __syncthreads();

  const int oy  = tid >> 3;
  const int ox0 = (tid & 7) << 3;

  {
    const float w0 = wsh[3], w1 = wsh[4], w2 = wsh[5], bz = wsh[38];
    for (int i = tid; i < 40*72; i += 256){
      int r = i / 72, x = i - r*72;
      sT2[r*74 + x] = __float2bfloat16(w0*sT1[r*73+x] + w1*sT1[(r+1)*73+x]
                                       + w2*sT1[(r+2)*73+x] + bz);
    }
    const float vb = wsh[41];
    float o8[8];
    #pragma unroll
    for (int j = 0; j < 8; j++) o8[j] = vb;
    #pragma unroll
    for (int rr = 0; rr < 3; rr++){
      const float wv = wsh[34 + rr];
      const __nv_bfloat16* row = sU1 + (oy+rr)*66 + ox0;
      #pragma unroll
      for (int p = 0; p < 4; p++){
        float2 u = ldbf2(row + 2*p);
        o8[2*p]   += wv*u.x;
        o8[2*p+1] += wv*u.y;
      }
    }
    const __nv_bfloat16* hx = xh + (long long)b*in_bs + (long long)c*HW
                            + (long long)(ty0+oy)*Wdim + tx0 + ox0;
    #pragma unroll
    for (int p = 0; p < 4; p++){
      float2 u = ldbf2(hx + 2*p);
      o8[2*p]   *= u.x;
      o8[2*p+1] *= u.y;
    }
    uint4 u;
    u.x = pkbf(o8[0], o8[1]); u.y = pkbf(o8[2], o8[3]);
    u.z = pkbf(o8[4], o8[5]); u.w = pkbf(o8[6], o8[7]);
    *(uint4*)(x3out + (long long)b*out_bs + (long long)c*HW
              + (long long)(ty0+oy)*Wdim + tx0 + ox0) = u;
  }
  __syncthreads();

  {
    const float bz = wsh[39];
    float a[8];
    #pragma unroll
    for (int j = 0; j < 8; j++) a[j] = bz;
    #pragma unroll
    for (int ky = 0; ky < 5; ky++){
      const __nv_bfloat16* row = sT2 + (oy + 2*ky)*74 + ox0;
      float buf[16];
      #pragma unroll
      for (int p = 0; p < 8; p++){
        float2 u = ldbf2(row + 2*p);
        buf[2*p] = u.x; buf[2*p+1] = u.y;
      }
      #pragma unroll
      for (int kx = 0; kx < 5; kx++){
        const float wv = wsh[6 + ky*5 + kx];
        #pragma unroll
        for (int j = 0; j < 8; j++) a[j] += wv * buf[kx*2 + j];
      }
    }
    uint4 u;
    u.x = pkbf(a[0], a[1]); u.y = pkbf(a[2], a[3]);
    u.z = pkbf(a[4], a[5]); u.w = pkbf(a[6], a[7]);
    *(uint4*)(l3pre + (long long)b*out_bs + (long long)c*HW
              + (long long)(ty0+oy)*Wdim + tx0 + ox0) = u;
  }
}

// ---------------------------------------------------------------------------
// branch-2: 64x64 tile; gate output pre-multiplied by xh. (r15, unchanged)
// ---------------------------------------------------------------------------
__global__ __launch_bounds__(512)
void branch2_kernel(const __nv_bfloat16* __restrict__ in, long long in_bs,
    const __nv_bfloat16* __restrict__ xh,
    const float* __restrict__ l5w1, const float* __restrict__ l5b1,
    const float* __restrict__ l5w2, const float* __restrict__ l5b2,
    const float* __restrict__ x5w,  const float* __restrict__ x5b,
    __nv_bfloat16* __restrict__ l5pre, __nv_bfloat16* __restrict__ x5out,
    long long out_bs)
{
  __shared__ __nv_bfloat16 sIN[80*82];
  __shared__ __nv_bfloat16 sV1[76*78];
  __shared__ float wsh[104];

  const int c = blockIdx.z & 63, b = blockIdx.z >> 6;
  const int ty0 = blockIdx.y * 64, tx0 = blockIdx.x * 64;
  const int tid = threadIdx.x;

  if (tid < 102){
    float v;
    if      (tid < 25) v = l5w1[c*25 + tid];
    else if (tid < 74) v = l5w2[c*49 + tid-25];
    else if (tid < 99) v = x5w[c*25 + tid-74];
    else if (tid == 99)  v = l5b1[c];
    else if (tid == 100) v = l5b2[c];
    else                 v = x5b[c];
    wsh[tid] = v;
  }

  const __nv_bfloat16* ip = in + (long long)b*in_bs + (long long)c*HW;
  const __nv_bfloat16 zb = __float2bfloat16(0.f);
  for (int i = tid; i < 80*80; i += 512){
    int sy = i / 80, sx = i - sy*80;
    int gy = ty0 + sy - 8, gx = tx0 + sx - 8;
    __nv_bfloat16 v = zb;
    if ((unsigned)gy < 128u && (unsigned)gx < 128u) v = ip[gy*Wdim + gx];
    sIN[sy*82 + sx] = v;
  }
  __syncthreads();

  const int oy  = tid >> 3;
  const int ox0 = (tid & 7) << 3;

  {
    const float bz = wsh[99];
    for (int g = tid; g < 76*19; g += 512){
      int r = g / 19, c4 = (g - r*19) << 2;
      float a0 = bz, a1 = bz, a2 = bz, a3 = bz;
      #pragma unroll
      for (int ky = 0; ky < 5; ky++){
        const __nv_bfloat16* row = sIN + (r+ky)*82 + c4;
        float buf[8];
        #pragma unroll
        for (int p = 0; p < 4; p++){
          float2 u = ldbf2(row + 2*p);
          buf[2*p] = u.x; buf[2*p+1] = u.y;
        }
        #pragma unroll
        for (int kx = 0; kx < 5; kx++){
          const float wv = wsh[ky*5+kx];
          a0 += wv*buf[kx+0];
          a1 += wv*buf[kx+1];
          a2 += wv*buf[kx+2];
          a3 += wv*buf[kx+3];
        }
      }
      uint32_t* d = (uint32_t*)(sV1 + r*78 + c4);
      d[0] = pkbf(a0, a1); d[1] = pkbf(a2, a3);
    }
    const float xb = wsh[101];
    float a[8];
    #pragma unroll
    for (int j = 0; j < 8; j++) a[j] = xb;
    #pragma unroll
    for (int ky = 0; ky < 5; ky++){
      const __nv_bfloat16* row = sIN + (oy+6+ky)*82 + ox0 + 6;
      float buf[12];
      #pragma unroll
      for (int p = 0; p < 6; p++){
        float2 u = ldbf2(row + 2*p);
        buf[2*p] = u.x; buf[2*p+1] = u.y;
      }
      #pragma unroll
      for (int kx = 0; kx < 5; kx++){
        const float wv = wsh[74 + ky*5 + kx];
        #pragma unroll
        for (int j = 0; j < 8; j++) a[j] += wv * buf[kx + j];
      }
    }
    const __nv_bfloat16* hx = xh + (long long)b*in_bs + (long long)c*HW
                            + (long long)(ty0+oy)*Wdim + tx0 + ox0;
    #pragma unroll
    for (int p = 0; p < 4; p++){
      float2 u = ldbf2(hx + 2*p);
      a[2*p]   *= u.x;
      a[2*p+1] *= u.y;
    }
    uint4 u;
    u.x = pkbf(a[0], a[1]); u.y = pkbf(a[2], a[3]);
    u.z = pkbf(a[4], a[5]); u.w = pkbf(a[6], a[7]);
    *(uint4*)(x5out + (long long)b*out_bs + (long long)c*HW
              + (long long)(ty0+oy)*Wdim + tx0 + ox0) = u;
  }
  __syncthreads();

  {
    const float bz = wsh[100];
    float a[8];
    #pragma unroll
    for (int j = 0; j < 8; j++) a[j] = bz;
    #pragma unroll
    for (int ky = 0; ky < 7; ky++){
      const __nv_bfloat16* row = sV1 + (oy + 2*ky)*78 + ox0;
      float buf[20];
      #pragma unroll
      for (int p = 0; p < 10; p++){
        float2 u = ldbf2(row + 2*p);
        buf[2*p] = u.x; buf[2*p+1] = u.y;
      }
      #pragma unroll
      for (int kx = 0; kx < 7; kx++){
        const float wv = wsh[25 + ky*7 + kx];
        #pragma unroll
        for (int j = 0; j < 8; j++) a[j] += wv * buf[kx*2 + j];
      }
    }
    uint4 u;
    u.x = pkbf(a[0], a[1]); u.y = pkbf(a[2], a[3]);
    u.z = pkbf(a[4], a[5]); u.w = pkbf(a[6], a[7]);
    *(uint4*)(l5pre + (long long)b*out_bs + (long long)c*HW
              + (long long)(ty0+oy)*Wdim + tx0 + ox0) = u;
  }
}

// ---------------------------------------------------------------------------
extern "C" void kernel_launch(void* const* d_in, const int* in_sizes, int n_in,
                              void* d_out, int out_size)
{
  const float* x    = (const float*)d_in[0];
  const float* ln_w = (const float*)d_in[1];
  const float* ln_b = (const float*)d_in[2];
  const float* scale= (const float*)d_in[3];
  const float* pf_w = (const float*)d_in[4];
  const float* pf_b = (const float*)d_in[5];
  const float* l3w1 = (const float*)d_in[6];
  const float* l3b1 = (const float*)d_in[7];
  const float* l3w2 = (const float*)d_in[8];
  const float* l3b2 = (const float*)d_in[9];
  const float* l3w3 = (const float*)d_in[10];
  const float* l3b3 = (const float*)d_in[11];
  const float* l3w4 = (const float*)d_in[12];
  const float* l3b4 = (const float*)d_in[13];
  const float* l5w1 = (const float*)d_in[14];
  const float* l5b1 = (const float*)d_in[15];
  const float* l5w2 = (const float*)d_in[16];
  const float* l5b2 = (const float*)d_in[17];
  const float* l5w3 = (const float*)d_in[18];
  const float* l5b3 = (const float*)d_in[19];
  const float* x3aw = (const float*)d_in[20];
  const float* x3ab = (const float*)d_in[21];
  const float* x3bw = (const float*)d_in[22];
  const float* x3bb = (const float*)d_in[23];
  const float* x5w  = (const float*)d_in[24];
  const float* x5b  = (const float*)d_in[25];
  const float* pl_w = (const float*)d_in[26];
  const float* pl_b = (const float*)d_in[27];
  float* out = (float*)d_out;

  __nv_bfloat16 *p_h, *p_t1, *p_x3;
  cudaGetSymbolAddress((void**)&p_h,  g_h);
  cudaGetSymbolAddress((void**)&p_t1, g_t1);
  cudaGetSymbolAddress((void**)&p_x3, g_x3);

  const long long BS_H = 256LL*HW, BS128 = 128LL*HW;

  // 1) pf: LN folded into W', x read once
  {
    cudaFuncSetAttribute((const void*)pf_kernel, cudaFuncAttributeMaxDynamicSharedMemorySize, PF_TOT);
    pf_kernel<<<dim3(64,16),1024,PF_TOT>>>(x, ln_w, ln_b, pf_w, pf_b, p_h, 4);
  }
  // 2) fused dw branches (gate outputs pre-multiplied by xh)
  branch1_kernel<<<dim3(2,4,16*64),256>>>(p_h, BS_H, p_h + 128LL*HW,
                                          l3w1,l3b1, l3w2,l3b2, l3w3,l3b3,
                                          x3aw,x3ab, x3bw,x3bb, p_t1, p_x3, BS128);
  branch2_kernel<<<dim3(2,2,16*64),512>>>(p_h + 64LL*HW, BS_H, p_h + 192LL*HW,
                                          l5w1,l5b1, l5w2,l5b2,
                                          x5w,x5b, p_t1 + 64LL*HW, p_x3 + 64LL*HW, BS128);
  // 3+4) fused attn+pl, 128-px tiles
  {
    cudaFuncSetAttribute((const void*)fuse2_kernel, cudaFuncAttributeMaxDynamicSharedMemorySize, F2_TOT);
    fuse2_kernel<<<dim3(32,16),1024,F2_TOT>>>(p_t1, p_x3,
                                              l3w4, l5w3, l3b4, l5b3,
                                              pl_w, pl_b, scale, x, out, 4);
  }
}

// round 17
// speedup vs baseline: 1.4015x; 1.4015x over previous
#include <cuda_runtime.h>
#include <cuda_bf16.h>
#include <cstdint>

#define HW   16384
#define Wdim 128

// ---------------- scratch (bf16 intermediates) ----------------
__device__ __nv_bfloat16 g_h [16ULL*256*16384];  // pf out: a(0..127) | xh(128..255)
__device__ __nv_bfloat16 g_t1[16ULL*128*16384];  // l3pre(0..63) | l5pre(64..127)
__device__ __nv_bfloat16 g_x3[16ULL*128*16384];  // gate*xh (0..127)

// ---------------- helpers ----------------
__device__ __forceinline__ uint32_t smem_u32(const void* p){
  uint32_t a;
  asm("{ .reg .u64 t; cvta.to.shared.u64 t, %1; cvt.u32.u64 %0, t; }" : "=r"(a) : "l"(p));
  return a;
}
__device__ __forceinline__ void cp16(uint32_t s, const void* g){
  asm volatile("cp.async.cg.shared.global [%0], [%1], 16;" :: "r"(s), "l"(g) : "memory");
}
__device__ __forceinline__ void cp_commit(){ asm volatile("cp.async.commit_group;" ::: "memory"); }
__device__ __forceinline__ void cp_wait0(){ asm volatile("cp.async.wait_group 0;" ::: "memory"); }
__device__ __forceinline__ void cp_wait1(){ asm volatile("cp.async.wait_group 1;" ::: "memory"); }
__device__ __forceinline__ void mma_bf16(float* d, const uint32_t* a, const uint32_t* b){
  asm volatile(
    "mma.sync.aligned.m16n8k16.row.col.f32.bf16.bf16.f32 "
    "{%0,%1,%2,%3}, {%4,%5,%6,%7}, {%8,%9}, {%0,%1,%2,%3};"
    : "+f"(d[0]), "+f"(d[1]), "+f"(d[2]), "+f"(d[3])
    : "r"(a[0]), "r"(a[1]), "r"(a[2]), "r"(a[3]), "r"(b[0]), "r"(b[1]));
}
__device__ __forceinline__ void ldsm4(uint32_t* r, uint32_t a){
  asm volatile("ldmatrix.sync.aligned.m8n8.x4.shared.b16 {%0,%1,%2,%3}, [%4];"
    : "=r"(r[0]), "=r"(r[1]), "=r"(r[2]), "=r"(r[3]) : "r"(a));
}
__device__ __forceinline__ void ldsm4t(uint32_t* r, uint32_t a){
  asm volatile("ldmatrix.sync.aligned.m8n8.x4.trans.shared.b16 {%0,%1,%2,%3}, [%4];"
    : "=r"(r[0]), "=r"(r[1]), "=r"(r[2]), "=r"(r[3]) : "r"(a));
}
__device__ __forceinline__ uint32_t pkbf(float a, float b){
  __nv_bfloat162 t = __floats2bfloat162_rn(a, b);
  return *reinterpret_cast<uint32_t*>(&t);
}
__device__ __forceinline__ float2 ldbf2(const __nv_bfloat16* p){
  return __bfloat1622float2(*(const __nv_bfloat162*)p);
}

// ---------------------------------------------------------------------------
// pf (r15): LN + 1x1 expand, all 256 oc per block, x read once.
// ---------------------------------------------------------------------------
#define PF_WS   0
#define PF_X0   69632
#define PF_X1   104448
#define PF_XN   139264
#define PF_LNW  157696
#define PF_LNB  158208
#define PF_MU   158720
#define PF_RS   159232
#define PF_PART 159744
#define PF_TOT  167936

__global__ __launch_bounds__(1024, 1)
void pf_kernel(const float* __restrict__ in,
               const float* __restrict__ lnw, const float* __restrict__ lnb,
               const float* __restrict__ w, const float* __restrict__ bias,
               __nv_bfloat16* __restrict__ out, int ntiles)
{
  extern __shared__ char smc[];
  __nv_bfloat16* Ws = (__nv_bfloat16*)(smc + PF_WS);
  float* Xb0 = (float*)(smc + PF_X0);
  float* Xb1 = (float*)(smc + PF_X1);
  __nv_bfloat16* Xn = (__nv_bfloat16*)(smc + PF_XN);
  float* sLNw  = (float*)(smc + PF_LNW);
  float* sLNb  = (float*)(smc + PF_LNB);
  float* sMu   = (float*)(smc + PF_MU);
  float* sRs   = (float*)(smc + PF_RS);
  float* sPart = (float*)(smc + PF_PART);
  const uint32_t sbase = smem_u32(smc);
  const uint32_t xu0 = sbase + PF_X0, xu1 = sbase + PF_X1;

  const int tid = threadIdx.x;
  const int wid = tid >> 5, lid = tid & 31;
  const int b   = blockIdx.y;

  for (int i = tid; i < 256*32; i += 1024){
    int oc = i >> 5, c4 = (i & 31) << 2;
    float4 v = *(const float4*)(w + oc*128 + c4);
    uint32_t* d = (uint32_t*)(Ws + oc*136 + c4);
    d[0] = pkbf(v.x, v.y); d[1] = pkbf(v.z, v.w);
  }
  if (tid < 128){ sLNw[tid] = lnw[tid]; sLNb[tid] = lnb[tid]; }

  const int wm = wid & 15, wn = wid >> 4;
  const int oc0 = wm*16, pxw = wn*32;
  const int r = lid >> 2, cq = lid & 3;
  const int mh = lid >> 3, rr = lid & 7;
  const int oA = oc0 + r, oB = oc0 + r + 8;
  const float bzA = bias[oA], bzB = bias[oB];

  const uint32_t aBase  = sbase + PF_WS
      + (uint32_t)(((oc0 + rr + (mh&1)*8)*136 + (mh>>1)*8) * 2);
  const uint32_t bBase0 = sbase + PF_XN
      + (uint32_t)(((rr + (mh&1)*8)*72 + pxw + (mh>>1)*8) * 2);
  const uint32_t bBase1 = bBase0 + 32;

  auto stage = [&](int t){
    const int px0 = (blockIdx.x * ntiles + t) * 64;
    const uint32_t xb = (t & 1) ? xu1 : xu0;
    const float* ipx = in + (size_t)b*(128LL*HW) + px0;
    #pragma unroll 2
    for (int i = tid; i < 128*16; i += 1024){
      int ic = i >> 4, pc = (i & 15) << 2;
      cp16(xb + (uint32_t)(ic*68 + pc)*4u, ipx + (size_t)ic*HW + pc);
    }
    cp_commit();
  };
  stage(0);

  for (int t = 0; t < ntiles; t++){
    if (t+1 < ntiles){ stage(t+1); cp_wait1(); }
    else             { cp_wait0(); }
    __syncthreads();
    float* Xs = (t & 1) ? Xb1 : Xb0;
    uint32_t* XsW = (uint32_t*)Xs;
    const int px0 = (blockIdx.x * ntiles + t) * 64;

    {
      const int px = tid & 63, q = tid >> 6;
      float s = 0.f, s2 = 0.f;
      #pragma unroll
      for (int ic = 0; ic < 8; ic++){
        float v = Xs[(q*8 + ic)*68 + px]; s += v; s2 += v*v;
      }
      sPart[tid] = s; sPart[1024 + tid] = s2;
    }
    __syncthreads();
    if (tid < 64){
      float ss = 0.f, qq = 0.f;
      #pragma unroll
      for (int j = 0; j < 16; j++){
        ss += sPart[tid + 64*j];
        qq += sPart[1024 + tid + 64*j];
      }
      float mu = ss * (1.f/128.f);
      sMu[tid] = mu;
      sRs[tid] = rsqrtf(qq*(1.f/128.f) - mu*mu + 1e-6f);
    }
    __syncthreads();

    #pragma unroll 4
    for (int i = tid; i < 128*32; i += 1024){
      int ch = i >> 5, pxp = (i & 31) << 1;
      float2 v = *(const float2*)(Xs + ch*68 + pxp);
      float wv = sLNw[ch], bv = sLNb[ch];
      float y0 = (v.x - sMu[pxp])   * (wv * sRs[pxp])   + bv;
      float y1 = (v.y - sMu[pxp+1]) * (wv * sRs[pxp+1]) + bv;
      *(uint32_t*)(Xn + ch*72 + pxp) = pkbf(y0, y1);
    }
    __syncthreads();

    float acc[4][4];
    #pragma unroll
    for (int ni = 0; ni < 4; ni++)
      #pragma unroll
      for (int j = 0; j < 4; j++) acc[ni][j] = 0.f;

    #pragma unroll
    for (int ks = 0; ks < 8; ks++){
      uint32_t af[4], b0[4], b1[4];
      ldsm4 (af, aBase  + (uint32_t)ks*32);
      ldsm4t(b0, bBase0 + (uint32_t)ks*2304);
      ldsm4t(b1, bBase1 + (uint32_t)ks*2304);
      mma_bf16(acc[0], af, b0);
      mma_bf16(acc[1], af, b0 + 2);
      mma_bf16(acc[2], af, b1);
      mma_bf16(acc[3], af, b1 + 2);
    }
    __syncthreads();

    {
      const int pw0 = (pxw >> 1) + cq;
      #pragma unroll
      for (int ni = 0; ni < 4; ni++){
        XsW[oA*34 + pw0 + ni*4] = pkbf(acc[ni][0] + bzA, acc[ni][1] + bzA);
        XsW[oB*34 + pw0 + ni*4] = pkbf(acc[ni][2] + bzB, acc[ni][3] + bzB);
      }
    }
    __syncthreads();

    __nv_bfloat16* ob = out + (size_t)b*256*HW + px0;
    for (int i = tid; i < 256*16; i += 1024){
      int oc = i >> 4, seg = i & 15;
      uint2 v = *(const uint2*)(XsW + oc*34 + seg*2);
      *(uint2*)(ob + (size_t)oc*HW + seg*4) = v;
    }
    __syncthreads();
  }
}

// ---------------------------------------------------------------------------
// fuse2 (r15): attn + pl, 64-px tiles, double-buffered Ts, 2 syncs/tile.
// ---------------------------------------------------------------------------
#define PT 72
#define F2_W1   0
#define F2_W2   18432
#define F2_PRE  53248
#define F2_GATE 90112
#define F2_T    126976
#define F2_TOT  163840
#define TBUF    18432

__global__ __launch_bounds__(1024, 1)
void fuse2_kernel(const __nv_bfloat16* __restrict__ pre,
                  const __nv_bfloat16* __restrict__ gate,
                  const float* __restrict__ w1A, const float* __restrict__ w1B,
                  const float* __restrict__ b1A, const float* __restrict__ b1B,
                  const float* __restrict__ plw, const float* __restrict__ plb,
                  const float* __restrict__ scal, const float* __restrict__ xres,
                  float* __restrict__ out, int ntiles)
{
  extern __shared__ char smc[];
  __nv_bfloat16* W1s = (__nv_bfloat16*)(smc + F2_W1);
  __nv_bfloat16* W2s = (__nv_bfloat16*)(smc + F2_W2);
  const uint32_t sbase = smem_u32(smc);

  const int tid = threadIdx.x;
  const int wid = tid >> 5, lid = tid & 31;
  const int b   = blockIdx.y;

  for (int i = tid; i < 128*16; i += 1024){
    int oc = i >> 4, k4 = (i & 15) << 2;
    float4 v = (oc < 64) ? *(const float4*)(w1A + oc*64 + k4)
                         : *(const float4*)(w1B + (oc-64)*64 + k4);
    uint32_t* d = (uint32_t*)(W1s + oc*PT + k4);
    d[0] = pkbf(v.x, v.y); d[1] = pkbf(v.z, v.w);
  }
  for (int i = tid; i < 128*32; i += 1024){
    int oc = i >> 5, c4 = (i & 31) << 2;
    float4 v = *(const float4*)(plw + oc*128 + c4);
    uint32_t* d = (uint32_t*)(W2s + oc*136 + c4);
    d[0] = pkbf(v.x, v.y); d[1] = pkbf(v.z, v.w);
  }

  const int wm = wid & 7, wn = wid >> 3;
  const int oc0 = wm*16, pxw = wn*16;
  const int r = lid >> 2, cq = lid & 3;
  const int mh = lid >> 3, rr = lid & 7;
  const int oA = oc0 + r, oB = oc0 + r + 8;
  const int koff = (oc0 >= 64) ? 64 : 0;

  const float bz1A = (oA < 64) ? b1A[oA] : b1B[oA-64];
  const float bz1B = (oB < 64) ? b1A[oB] : b1B[oB-64];
  const float bz2A = plb[oA], bz2B = plb[oB];
  const float scA  = scal[oA], scB = scal[oB];

  const uint32_t a1Base = sbase + F2_W1
      + (uint32_t)(((oc0 + rr + (mh&1)*8)*PT + (mh>>1)*8) * 2);
  const uint32_t a2Base = sbase + F2_W2
      + (uint32_t)(((oc0 + rr + (mh&1)*8)*136 + (mh>>1)*8) * 2);
  const uint32_t b1Off  =
      (uint32_t)(((koff + rr + (mh&1)*8)*PT + pxw + (mh>>1)*8) * 2);
  const uint32_t b2Off  = sbase + F2_T
      + (uint32_t)(((rr + (mh&1)*8)*PT + pxw + (mh>>1)*8) * 2);

  auto stage = [&](int t){
    const int px0 = (blockIdx.x * ntiles + t) * 64;
    const uint32_t buf = (uint32_t)(t & 1) * TBUF;
    const __nv_bfloat16* p1 = pre  + (size_t)b*(128LL*HW) + px0;
    const __nv_bfloat16* p2 = gate + (size_t)b*(128LL*HW) + px0;
    for (int i = tid; i < 128*8; i += 1024){
      int ic = i >> 3, pc = (i & 7) << 3;
      uint32_t off = (uint32_t)(ic*PT + pc)*2u;
      cp16(sbase + F2_PRE  + buf + off, p1 + (size_t)ic*HW + pc);
      cp16(sbase + F2_GATE + buf + off, p2 + (size_t)ic*HW + pc);
    }
    cp_commit();
  };
  stage(0);

  for (int t = 0; t < ntiles; t++){
    if (t+1 < ntiles){ stage(t+1); cp_wait1(); }
    else             { cp_wait0(); }
    __syncthreads();
    const int buf = (t & 1);
    const __nv_bfloat16* Gs = (const __nv_bfloat16*)(smc + F2_GATE + buf*TBUF);
    __nv_bfloat16* Ts = (__nv_bfloat16*)(smc + F2_T + buf*TBUF);
    const uint32_t b1Base = sbase + F2_PRE + (uint32_t)buf*TBUF + b1Off;
    const uint32_t b2Base = b2Off + (uint32_t)buf*TBUF;
    const int px0 = (blockIdx.x * ntiles + t) * 64;

    float a1[2][4];
    #pragma unroll
    for (int ni = 0; ni < 2; ni++)
      #pragma unroll
      for (int j = 0; j < 4; j++) a1[ni][j] = 0.f;

    #pragma unroll
    for (int ks = 0; ks < 4; ks++){
      uint32_t af[4], bf[4];
      ldsm4 (af, a1Base + (uint32_t)ks*32);
      ldsm4t(bf, b1Base + (uint32_t)ks*2304);
      mma_bf16(a1[0], af, bf);
      mma_bf16(a1[1], af, bf + 2);
    }

    #pragma unroll
    for (int ni = 0; ni < 2; ni++){
      const int pxl = pxw + ni*8 + cq*2;
      float2 gA = ldbf2(Gs + oA*PT + pxl);
      *(uint32_t*)(Ts + oA*PT + pxl) =
        pkbf((a1[ni][0] + bz1A)*gA.x, (a1[ni][1] + bz1A)*gA.y);
      float2 gB = ldbf2(Gs + oB*PT + pxl);
      *(uint32_t*)(Ts + oB*PT + pxl) =
        pkbf((a1[ni][2] + bz1B)*gB.x, (a1[ni][3] + bz1B)*gB.y);
    }
    __syncthreads();

    float a2[2][4];
    #pragma unroll
    for (int ni = 0; ni < 2; ni++)
      #pragma unroll
      for (int j = 0; j < 4; j++) a2[ni][j] = 0.f;

    #pragma unroll
    for (int ks = 0; ks < 8; ks++){
      uint32_t af[4], bf[4];
      ldsm4 (af, a2Base + (uint32_t)ks*32);
      ldsm4t(bf, b2Base + (uint32_t)ks*2304);
      mma_bf16(a2[0], af, bf);
      mma_bf16(a2[1], af, bf + 2);
    }

    {
      const int pc = px0 + pxw + cq*2;
      float* opA = out + ((size_t)b*128 + oA)*HW + pc;
      float* opB = out + ((size_t)b*128 + oB)*HW + pc;
      const float* shA = xres + ((size_t)b*128 + oA)*HW + pc;
      const float* shB = xres + ((size_t)b*128 + oB)*HW + pc;
      #pragma unroll
      for (int ni = 0; ni < 2; ni++){
        float2 sA = *(const float2*)(shA + ni*8);
        float2 sB = *(const float2*)(shB + ni*8);
        *(float2*)(opA + ni*8) = make_float2((a2[ni][0] + bz2A)*scA + sA.x,
                                             (a2[ni][1] + bz2A)*scA + sA.y);
        *(float2*)(opB + ni*8) = make_float2((a2[ni][2] + bz2B)*scB + sB.x,
                                             (a2[ni][3] + bz2B)*scB + sB.y);
      }
    }
    // Ts double-buffered: no trailing sync
  }
}

// ---------------------------------------------------------------------------
// branch-1: NEW 64x64 tile, 512 threads, all-bf16 smem (pair-load strips).
// gate output pre-multiplied by xh.
// ---------------------------------------------------------------------------
__global__ __launch_bounds__(512)
void branch1_kernel(const __nv_bfloat16* __restrict__ in, long long in_bs,
    const __nv_bfloat16* __restrict__ xh,
    const float* __restrict__ l3w1, const float* __restrict__ l3b1,
    const float* __restrict__ l3w2, const float* __restrict__ l3b2,
    const float* __restrict__ l3w3, const float* __restrict__ l3b3,
    const float* __restrict__ x3aw, const float* __restrict__ x3ab,
    const float* __restrict__ x3bw, const float* __restrict__ x3bb,
    __nv_bfloat16* __restrict__ l3pre, __nv_bfloat16* __restrict__ x3out,
    long long out_bs)
{
  __shared__ __nv_bfloat16 sIN[74*76];   // 74 rows x 74 cols used
  __shared__ __nv_bfloat16 sT1[74*74];   // 74 rows x 72 cols used
  __shared__ __nv_bfloat16 sU1[66*66];   // 66 rows x 64 cols used
  __shared__ __nv_bfloat16 sT2[72*74];   // 72 rows x 72 cols used
  __shared__ float wsh[42];

  const int c = blockIdx.z & 63, b = blockIdx.z >> 6;
  const int ty0 = blockIdx.y * 64, tx0 = blockIdx.x * 64;
  const int tid = threadIdx.x;

  if (tid < 42){
    float v;
    if      (tid < 3)  v = l3w1[c*3 + tid];
    else if (tid < 6)  v = l3w2[c*3 + tid-3];
    else if (tid < 31) v = l3w3[c*25 + tid-6];
    else if (tid < 34) v = x3aw[c*3 + tid-31];
    else if (tid < 37) v = x3bw[c*3 + tid-34];
    else if (tid == 37) v = l3b1[c];
    else if (tid == 38) v = l3b2[c];
    else if (tid == 39) v = l3b3[c];
    else if (tid == 40) v = x3ab[c];
    else                v = x3bb[c];
    wsh[tid] = v;
  }

  const __nv_bfloat16* ip = in + (long long)b*in_bs + (long long)c*HW;
  const __nv_bfloat16 zb = __float2bfloat16(0.f);
  for (int i = tid; i < 74*74; i += 512){
    int sy = i / 74, sx = i - sy*74;
    int gy = ty0 + sy - 5, gx = tx0 + sx - 5;
    __nv_bfloat16 v = zb;
    if ((unsigned)gy < 128u && (unsigned)gx < 128u) v = ip[gy*Wdim + gx];
    sIN[sy*76 + sx] = v;
  }
  __syncthreads();

  // t1 (74 rows x 72 cols): 1x3 over sIN, strips of 4
  {
    const float w0 = wsh[0], w1 = wsh[1], w2 = wsh[2], bz = wsh[37];
    for (int g = tid; g < 74*18; g += 512){
      int rr2 = g / 18, c4 = (g - rr2*18) << 2;
      const __nv_bfloat16* row = sIN + rr2*76 + c4;
      float buf[8];
      #pragma unroll
      for (int p = 0; p < 4; p++){
        float2 u = ldbf2(row + 2*p);
        buf[2*p] = u.x; buf[2*p+1] = u.y;
      }
      float a0 = w0*buf[0] + w1*buf[1] + w2*buf[2] + bz;
      float a1 = w0*buf[1] + w1*buf[2] + w2*buf[3] + bz;
      float a2 = w0*buf[2] + w1*buf[3] + w2*buf[4] + bz;
      float a3 = w0*buf[3] + w1*buf[4] + w2*buf[5] + bz;
      uint32_t* d = (uint32_t*)(sT1 + rr2*74 + c4);
      d[0] = pkbf(a0, a1); d[1] = pkbf(a2, a3);
    }
    // u1 (66 rows x 64 cols): 1x3 gate pre-conv
    const float a0 = wsh[31], a1 = wsh[32], a2 = wsh[33], ab = wsh[40];
    for (int i = tid; i < 66*64; i += 512){
      int rr2 = i >> 6, x = i & 63;
      const __nv_bfloat16* s = sIN + (rr2+4)*76 + x + 4;
      float v = a0*__bfloat162float(s[0]) + a1*__bfloat162float(s[1])
              + a2*__bfloat162float(s[2]) + ab;
      sU1[rr2*66 + x] = __float2bfloat16(v);
    }
  }
  __syncthreads();

  const int oy  = tid >> 3;              // 0..63
  const int ox0 = (tid & 7) << 3;        // 0..56

  {
    // t2 (72 rows x 72 cols): 3x1 over sT1, strips of 4
    const float w0 = wsh[3], w1 = wsh[4], w2 = wsh[5], bz = wsh[38];
    for (int g = tid; g < 72*18; g += 512){
      int rr2 = g / 18, c4 = (g - rr2*18) << 2;
      float2 r0a = ldbf2(sT1 + rr2*74 + c4),     r0b = ldbf2(sT1 + rr2*74 + c4 + 2);
      float2 r1a = ldbf2(sT1 + (rr2+1)*74 + c4), r1b = ldbf2(sT1 + (rr2+1)*74 + c4 + 2);
      float2 r2a = ldbf2(sT1 + (rr2+2)*74 + c4), r2b = ldbf2(sT1 + (rr2+2)*74 + c4 + 2);
      float a0 = w0*r0a.x + w1*r1a.x + w2*r2a.x + bz;
      float a1 = w0*r0a.y + w1*r1a.y + w2*r2a.y + bz;
      float a2 = w0*r0b.x + w1*r1b.x + w2*r2b.x + bz;
      float a3 = w0*r0b.y + w1*r1b.y + w2*r2b.y + bz;
      uint32_t* d = (uint32_t*)(sT2 + rr2*74 + c4);
      d[0] = pkbf(a0, a1); d[1] = pkbf(a2, a3);
    }
    // gate x3out (3x1 over sU1) * xh
    const float vb = wsh[41];
    float o8[8];
    #pragma unroll
    for (int j = 0; j < 8; j++) o8[j] = vb;
    #pragma unroll
    for (int rr2 = 0; rr2 < 3; rr2++){
      const float wv = wsh[34 + rr2];
      const __nv_bfloat16* row = sU1 + (oy+rr2)*66 + ox0;
      #pragma unroll
      for (int p = 0; p < 4; p++){
        float2 u = ldbf2(row + 2*p);
        o8[2*p]   += wv*u.x;
        o8[2*p+1] += wv*u.y;
      }
    }
    const __nv_bfloat16* hx = xh + (long long)b*in_bs + (long long)c*HW
                            + (long long)(ty0+oy)*Wdim + tx0 + ox0;
    #pragma unroll
    for (int p = 0; p < 4; p++){
      float2 u = ldbf2(hx + 2*p);
      o8[2*p]   *= u.x;
      o8[2*p+1] *= u.y;
    }
    uint4 u;
    u.x = pkbf(o8[0], o8[1]); u.y = pkbf(o8[2], o8[3]);
    u.z = pkbf(o8[4], o8[5]); u.w = pkbf(o8[6], o8[7]);
    *(uint4*)(x3out + (long long)b*out_bs + (long long)c*HW
              + (long long)(ty0+oy)*Wdim + tx0 + ox0) = u;
  }
  __syncthreads();

  {
    // l3pre: 5x5 dil2 over sT2
    const float bz = wsh[39];
    float a[8];
    #pragma unroll
    for (int j = 0; j < 8; j++) a[j] = bz;
    #pragma unroll
    for (int ky = 0; ky < 5; ky++){
      const __nv_bfloat16* row = sT2 + (oy + 2*ky)*74 + ox0;
      float buf[16];
      #pragma unroll
      for (int p = 0; p < 8; p++){
        float2 u = ldbf2(row + 2*p);
        buf[2*p] = u.x; buf[2*p+1] = u.y;
      }
      #pragma unroll
      for (int kx = 0; kx < 5; kx++){
        const float wv = wsh[6 + ky*5 + kx];
        #pragma unroll
        for (int j = 0; j < 8; j++) a[j] += wv * buf[kx*2 + j];
      }
    }
    uint4 u;
    u.x = pkbf(a[0], a[1]); u.y = pkbf(a[2], a[3]);
    u.z = pkbf(a[4], a[5]); u.w = pkbf(a[6], a[7]);
    *(uint4*)(l3pre + (long long)b*out_bs + (long long)c*HW
              + (long long)(ty0+oy)*Wdim + tx0 + ox0) = u;
  }
}

// ---------------------------------------------------------------------------
// branch-2 (r15): 64x64 tile; gate output pre-multiplied by xh.
// ---------------------------------------------------------------------------
__global__ __launch_bounds__(512)
void branch2_kernel(const __nv_bfloat16* __restrict__ in, long long in_bs,
    const __nv_bfloat16* __restrict__ xh,
    const float* __restrict__ l5w1, const float* __restrict__ l5b1,
    const float* __restrict__ l5w2, const float* __restrict__ l5b2,
    const float* __restrict__ x5w,  const float* __restrict__ x5b,
    __nv_bfloat16* __restrict__ l5pre, __nv_bfloat16* __restrict__ x5out,
    long long out_bs)
{
  __shared__ __nv_bfloat16 sIN[80*82];
  __shared__ __nv_bfloat16 sV1[76*78];
  __shared__ float wsh[104];

  const int c = blockIdx.z & 63, b = blockIdx.z >> 6;
  const int ty0 = blockIdx.y * 64, tx0 = blockIdx.x * 64;
  const int tid = threadIdx.x;

  if (tid < 102){
    float v;
    if      (tid < 25) v = l5w1[c*25 + tid];
    else if (tid < 74) v = l5w2[c*49 + tid-25];
    else if (tid < 99) v = x5w[c*25 + tid-74];
    else if (tid == 99)  v = l5b1[c];
    else if (tid == 100) v = l5b2[c];
    else                 v = x5b[c];
    wsh[tid] = v;
  }

  const __nv_bfloat16* ip = in + (long long)b*in_bs + (long long)c*HW;
  const __nv_bfloat16 zb = __float2bfloat16(0.f);
  for (int i = tid; i < 80*80; i += 512){
    int sy = i / 80, sx = i - sy*80;
    int gy = ty0 + sy - 8, gx = tx0 + sx - 8;
    __nv_bfloat16 v = zb;
    if ((unsigned)gy < 128u && (unsigned)gx < 128u) v = ip[gy*Wdim + gx];
    sIN[sy*82 + sx] = v;
  }
  __syncthreads();

  const int oy  = tid >> 3;
  const int ox0 = (tid & 7) << 3;

  {
    const float bz = wsh[99];
    for (int g = tid; g < 76*19; g += 512){
      int r = g / 19, c4 = (g - r*19) << 2;
      float a0 = bz, a1 = bz, a2 = bz, a3 = bz;
      #pragma unroll
      for (int ky = 0; ky < 5; ky++){
        const __nv_bfloat16* row = sIN + (r+ky)*82 + c4;
        float buf[8];
        #pragma unroll
        for (int p = 0; p < 4; p++){
          float2 u = ldbf2(row + 2*p);
          buf[2*p] = u.x; buf[2*p+1] = u.y;
        }
        #pragma unroll
        for (int kx = 0; kx < 5; kx++){
          const float wv = wsh[ky*5+kx];
          a0 += wv*buf[kx+0];
          a1 += wv*buf[kx+1];
          a2 += wv*buf[kx+2];
          a3 += wv*buf[kx+3];
        }
      }
      uint32_t* d = (uint32_t*)(sV1 + r*78 + c4);
      d[0] = pkbf(a0, a1); d[1] = pkbf(a2, a3);
    }
    const float xb = wsh[101];
    float a[8];
    #pragma unroll
    for (int j = 0; j < 8; j++) a[j] = xb;
    #pragma unroll
    for (int ky = 0; ky < 5; ky++){
      const __nv_bfloat16* row = sIN + (oy+6+ky)*82 + ox0 + 6;
      float buf[12];
      #pragma unroll
      for (int p = 0; p < 6; p++){
        float2 u = ldbf2(row + 2*p);
        buf[2*p] = u.x; buf[2*p+1] = u.y;
      }
      #pragma unroll
      for (int kx = 0; kx < 5; kx++){
        const float wv = wsh[74 + ky*5 + kx];
        #pragma unroll
        for (int j = 0; j < 8; j++) a[j] += wv * buf[kx + j];
      }
    }
    const __nv_bfloat16* hx = xh + (long long)b*in_bs + (long long)c*HW
                            + (long long)(ty0+oy)*Wdim + tx0 + ox0;
    #pragma unroll
    for (int p = 0; p < 4; p++){
      float2 u = ldbf2(hx + 2*p);
      a[2*p]   *= u.x;
      a[2*p+1] *= u.y;
    }
    uint4 u;
    u.x = pkbf(a[0], a[1]); u.y = pkbf(a[2], a[3]);
    u.z = pkbf(a[4], a[5]); u.w = pkbf(a[6], a[7]);
    *(uint4*)(x5out + (long long)b*out_bs + (long long)c*HW
              + (long long)(ty0+oy)*Wdim + tx0 + ox0) = u;
  }
  __syncthreads();

  {
    const float bz = wsh[100];
    float a[8];
    #pragma unroll
    for (int j = 0; j < 8; j++) a[j] = bz;
    #pragma unroll
    for (int ky = 0; ky < 7; ky++){
      const __nv_bfloat16* row = sV1 + (oy + 2*ky)*78 + ox0;
      float buf[20];
      #pragma unroll
      for (int p = 0; p < 10; p++){
        float2 u = ldbf2(row + 2*p);
        buf[2*p] = u.x; buf[2*p+1] = u.y;
      }
      #pragma unroll
      for (int kx = 0; kx < 7; kx++){
        const float wv = wsh[25 + ky*7 + kx];
        #pragma unroll
        for (int j = 0; j < 8; j++) a[j] += wv * buf[kx*2 + j];
      }
    }
    uint4 u;
    u.x = pkbf(a[0], a[1]); u.y = pkbf(a[2], a[3]);
    u.z = pkbf(a[4], a[5]); u.w = pkbf(a[6], a[7]);
    *(uint4*)(l5pre + (long long)b*out_bs + (long long)c*HW
              + (long long)(ty0+oy)*Wdim + tx0 + ox0) = u;
  }
}

// ---------------------------------------------------------------------------
extern "C" void kernel_launch(void* const* d_in, const int* in_sizes, int n_in,
                              void* d_out, int out_size)
{
  const float* x    = (const float*)d_in[0];
  const float* ln_w = (const float*)d_in[1];
  const float* ln_b = (const float*)d_in[2];
  const float* scale= (const float*)d_in[3];
  const float* pf_w = (const float*)d_in[4];
  const float* pf_b = (const float*)d_in[5];
  const float* l3w1 = (const float*)d_in[6];
  const float* l3b1 = (const float*)d_in[7];
  const float* l3w2 = (const float*)d_in[8];
  const float* l3b2 = (const float*)d_in[9];
  const float* l3w3 = (const float*)d_in[10];
  const float* l3b3 = (const float*)d_in[11];
  const float* l3w4 = (const float*)d_in[12];
  const float* l3b4 = (const float*)d_in[13];
  const float* l5w1 = (const float*)d_in[14];
  const float* l5b1 = (const float*)d_in[15];
  const float* l5w2 = (const float*)d_in[16];
  const float* l5b2 = (const float*)d_in[17];
  const float* l5w3 = (const float*)d_in[18];
  const float* l5b3 = (const float*)d_in[19];
  const float* x3aw = (const float*)d_in[20];
  const float* x3ab = (const float*)d_in[21];
  const float* x3bw = (const float*)d_in[22];
  const float* x3bb = (const float*)d_in[23];
  const float* x5w  = (const float*)d_in[24];
  const float* x5b  = (const float*)d_in[25];
  const float* pl_w = (const float*)d_in[26];
  const float* pl_b = (const float*)d_in[27];
  float* out = (float*)d_out;

  __nv_bfloat16 *p_h, *p_t1, *p_x3;
  cudaGetSymbolAddress((void**)&p_h,  g_h);
  cudaGetSymbolAddress((void**)&p_t1, g_t1);
  cudaGetSymbolAddress((void**)&p_x3, g_x3);

  const long long BS_H = 256LL*HW, BS128 = 128LL*HW;

  // 1) pf: LN + expand, x read once
  {
    cudaFuncSetAttribute((const void*)pf_kernel, cudaFuncAttributeMaxDynamicSharedMemorySize, PF_TOT);
    pf_kernel<<<dim3(64,16),1024,PF_TOT>>>(x, ln_w, ln_b, pf_w, pf_b, p_h, 4);
  }
  // 2) fused dw branches (gate outputs pre-multiplied by xh)
  branch1_kernel<<<dim3(2,2,16*64),512>>>(p_h, BS_H, p_h + 128LL*HW,
                                          l3w1,l3b1, l3w2,l3b2, l3w3,l3b3,
                                          x3aw,x3ab, x3bw,x3bb, p_t1, p_x3, BS128);
  branch2_kernel<<<dim3(2,2,16*64),512>>>(p_h + 64LL*HW, BS_H, p_h + 192LL*HW,
                                          l5w1,l5b1, l5w2,l5b2,
                                          x5w,x5b, p_t1 + 64LL*HW, p_x3 + 64LL*HW, BS128);
  // 3+4) fused attn+pl (r15 64-px version)
  {
    cudaFuncSetAttribute((const void*)fuse2_kernel, cudaFuncAttributeMaxDynamicSharedMemorySize, F2_TOT);
    fuse2_kernel<<<dim3(64,16),1024,F2_TOT>>>(p_t1, p_x3,
                                              l3w4, l5w3, l3b4, l5b3,
                                              pl_w, pl_b, scale, x, out, 4);
  }
}